// round 13
// baseline (speedup 1.0000x reference)
#include <cuda_runtime.h>
#include <cuda_bf16.h>

// torchSOM: sequential SOM training, 2000 iterations, single persistent CTA.
// nodes [1024,32] live NEGATED in registers (1 thread = 1 node row).
// All arithmetic replicates XLA-GPU rounding bit-for-bit:
//   dist: per-lane square (mul.rn) + shfl-down-tree association (16,8,4,2,1),
//         then sqrt.rn; update: un-fused mul.rn + add.rn; exact alpha/threshold chain.

#define DDIM 32
#define NITER_C 2000

typedef unsigned long long u64;
typedef unsigned int u32;

__device__ __forceinline__ u64 pack2(float lo, float hi) {
    u64 r;
    asm("mov.b64 %0, {%1, %2};" : "=l"(r) : "f"(lo), "f"(hi));
    return r;
}
__device__ __forceinline__ void unpack2(u64 v, float& lo, float& hi) {
    asm("mov.b64 {%0, %1}, %2;" : "=f"(lo), "=f"(hi) : "l"(v));
}
// Packed IEEE-rn f32x2 ops (per-lane semantics identical to scalar rn ops).
#define ADD2(out, a, b) \
    asm("add.rn.f32x2 %0, %1, %2;" : "=l"(out) : "l"(a), "l"(b))
#define MUL2(out, a, b) \
    asm("mul.rn.f32x2 %0, %1, %2;" : "=l"(out) : "l"(a), "l"(b))

__global__ __launch_bounds__(1024, 1)
void som_train_kernel(const float* __restrict__ data,
                      const float* __restrict__ nodes,
                      const int* __restrict__ rand_indices,
                      float* __restrict__ out)
{
    // x row triple buffer: write at iter k start is separated from the last
    // conflicting read (iter k-2's update loop) by iter k-1's barriers.
    __shared__ __align__(16) float xs[3][DDIM];
    __shared__ u32 wbits[32];
    __shared__ u32 widx[32];
    __shared__ int winner;

    const int tid  = threadIdx.x;
    const int lane = tid & 31;
    const int wid  = tid >> 5;
    const int mr   = tid >> 5;   // lattice row of this node
    const int mc   = tid & 31;   // lattice col of this node

    // Load this thread's node row, negated (negation is exact), packed.
    u64 nn[16];
#pragma unroll
    for (int j = 0; j < 16; j++) {
        float a = nodes[tid * DDIM + 2 * j];
        float b = nodes[tid * DDIM + 2 * j + 1];
        nn[j] = pack2(-a, -b);
    }

    // Preload x for iteration 0.
    if (tid < DDIM) {
        int i0 = rand_indices[0];
        xs[0][tid] = data[(size_t)i0 * DDIM + tid];
    }
    __syncthreads();

    float th = 20.0f;  // THRESH0

    for (int k = 0; k < NITER_C; k++) {
        const u64* __restrict__ x2 = (const u64*)xs[k % 3];

        // Prefetch next iteration's x row (warp 31, overlapped with compute).
        if (tid >= 992 && (k + 1) < NITER_C) {
            int ni = rand_indices[k + 1];
            xs[(k + 1) % 3][tid - 992] = data[(size_t)ni * DDIM + (tid - 992)];
        }

        // ---- diff (x - node via x + (-node): bitwise == IEEE sub) ----
        u64 df[16];
        u64 m[16];
#pragma unroll
        for (int j = 0; j < 16; j++) {
            ADD2(df[j], x2[j], nn[j]);     // diff
            MUL2(m[j], df[j], df[j]);      // per-lane square, single rn (no FMA)
        }
        // ---- XLA shfl.down(16,8,4,2,1) tree association ----
        // lanes (i, i+16) share parity -> packed offsets 8,4,2,1; final lo+hi
        // is the offset-1 step.
#pragma unroll
        for (int j = 0; j < 8; j++) ADD2(m[j], m[j], m[j + 8]);   // +t[i+16]
#pragma unroll
        for (int j = 0; j < 4; j++) ADD2(m[j], m[j], m[j + 4]);   // +s[i+8]
#pragma unroll
        for (int j = 0; j < 2; j++) ADD2(m[j], m[j], m[j + 2]);   // +s[i+4]
        ADD2(m[0], m[0], m[1]);                                   // +s[i+2]
        float lo, hi;
        unpack2(m[0], lo, hi);
        float ss   = __fadd_rn(lo, hi);                           // +s[i+1]
        float dist = __fsqrt_rn(ss);   // correctly-rounded, matches XLA sqrt

        // ---- block argmin on dist, ties -> lowest node index ----
        // dist >= 0, so float bits are order-isomorphic to u32.
        u32 bits = __float_as_uint(dist);
        u32 wmin = __reduce_min_sync(0xffffffffu, bits);
        u32 ball = __ballot_sync(0xffffffffu, bits == wmin);
        if (lane == 0) {
            wbits[wid] = wmin;
            widx[wid]  = (u32)((wid << 5) + (__ffs(ball) - 1));
        }
        __syncthreads();  // bar1
        if (wid == 0) {
            u32 b  = wbits[lane];
            u32 m2 = __reduce_min_sync(0xffffffffu, b);
            u32 bl = __ballot_sync(0xffffffffu, b == m2);
            if (lane == 0) winner = (int)widx[__ffs(bl) - 1];
        }
        __syncthreads();  // bar2
        const int nearest = winner;

        // ---- deterministic threshold / alpha schedule (exact rn chain) ----
        th = fmaxf(th, 0.5f);
        float kf    = (float)k;                                   // exact
        float alpha = __fsub_rn(0.05f,
                        __fmul_rn(0.04f, __fdiv_rn(kf, 2000.0f)));

        // ---- masked neighborhood update: Chebyshev lattice distance ----
        int dr   = mr - (nearest >> 5); if (dr < 0) dr = -dr;
        int dc   = mc - (nearest & 31); if (dc < 0) dc = -dc;
        int cheb = dr > dc ? dr : dc;
        if ((float)cheb <= th) {
            // reference: n' = rn(n + rn(diff*alpha)); negated storage:
            // nn' = rn(nn + rn(diff*(-alpha))) — bit-identical under negation.
            u64 na = pack2(-alpha, -alpha);
#pragma unroll
            for (int j = 0; j < 16; j++) {
                u64 p;
                MUL2(p, df[j], na);
                ADD2(nn[j], nn[j], p);
            }
        }
        th = __fadd_rn(th, -0.00975f);  // THRESH_STEP
    }

    // ---- write final nodes (un-negate, exact) ----
#pragma unroll
    for (int j = 0; j < 16; j++) {
        float a, b;
        unpack2(nn[j], a, b);
        out[tid * DDIM + 2 * j]     = -a;
        out[tid * DDIM + 2 * j + 1] = -b;
    }
}

extern "C" void kernel_launch(void* const* d_in, const int* in_sizes, int n_in,
                              void* d_out, int out_size) {
    // Robust input binding by element count:
    // data 500000*32, nodes 1024*32, nhbrdist 1024*1024 (unused), rand 2000.
    const float* data   = nullptr;
    const float* nodes  = nullptr;
    const int*   ridx   = nullptr;
    for (int i = 0; i < n_in; i++) {
        if      (in_sizes[i] == 500000 * 32) data  = (const float*)d_in[i];
        else if (in_sizes[i] == 1024 * 32)   nodes = (const float*)d_in[i];
        else if (in_sizes[i] == 2000)        ridx  = (const int*)d_in[i];
    }
    som_train_kernel<<<1, 1024>>>(data, nodes, ridx, (float*)d_out);
}

// round 14
// speedup vs baseline: 1.7972x; 1.7972x over previous
#include <cuda_runtime.h>
#include <cuda_bf16.h>

// torchSOM: sequential SOM training, 2000 iterations, single persistent CTA.
// nodes [1024,32] live NEGATED in registers (1 thread = 1 node row).
// Bit-exact XLA-GPU rounding: per-lane square (mul.rn) + shfl-down-tree
// association (16,8,4,2,1) + sqrt.rn; un-fused mul/add update; exact schedule.
// R13: restructured to fit 64 regs/thread (1024 thr) with NO spills:
//  - reduction tree fused into the diff loop (4 accumulators, same association)
//  - update recomputes diff (nn unchanged since dist -> bit-identical)
//  - alpha (fdiv) computed once in warp 0, broadcast via smem on bar2

#define DDIM 32
#define NITER_C 2000

typedef unsigned long long u64;
typedef unsigned int u32;

__device__ __forceinline__ u64 pack2(float lo, float hi) {
    u64 r;
    asm("mov.b64 %0, {%1, %2};" : "=l"(r) : "f"(lo), "f"(hi));
    return r;
}
__device__ __forceinline__ void unpack2(u64 v, float& lo, float& hi) {
    asm("mov.b64 {%0, %1}, %2;" : "=f"(lo), "=f"(hi) : "l"(v));
}
// Packed IEEE-rn f32x2 ops (per-lane semantics identical to scalar rn ops).
#define ADD2(out, a, b) \
    asm("add.rn.f32x2 %0, %1, %2;" : "=l"(out) : "l"(a), "l"(b))
#define MUL2(out, a, b) \
    asm("mul.rn.f32x2 %0, %1, %2;" : "=l"(out) : "l"(a), "l"(b))

__global__ __launch_bounds__(1024, 1)
void som_train_kernel(const float* __restrict__ data,
                      const float* __restrict__ nodes,
                      const int* __restrict__ rand_indices,
                      float* __restrict__ out)
{
    // x row triple buffer: the write at iter k+1 start is separated from the
    // last conflicting read (iter k-1's update loop) by iter k's barriers.
    __shared__ __align__(16) float xs[3][DDIM];
    __shared__ u32 wbits[32];
    __shared__ u32 widx[32];
    __shared__ int winner;
    __shared__ float neg_alpha_sh;

    const int tid  = threadIdx.x;
    const int lane = tid & 31;
    const int wid  = tid >> 5;
    const int mr   = tid >> 5;   // lattice row of this node
    const int mc   = tid & 31;   // lattice col of this node

    // Load this thread's node row, negated (negation is exact), packed.
    u64 nn[16];
#pragma unroll
    for (int j = 0; j < 16; j++) {
        float a = nodes[tid * DDIM + 2 * j];
        float b = nodes[tid * DDIM + 2 * j + 1];
        nn[j] = pack2(-a, -b);
    }

    // Preload x for iteration 0.
    if (tid < DDIM) {
        int i0 = rand_indices[0];
        xs[0][tid] = data[(size_t)i0 * DDIM + tid];
    }
    __syncthreads();

    float th = 20.0f;  // THRESH0

    for (int k = 0; k < NITER_C; k++) {
        const u64* __restrict__ x2 = (const u64*)xs[k % 3];

        // Prefetch next iteration's x row (warp 31, overlapped with compute).
        if (tid >= 992 && (k + 1) < NITER_C) {
            int ni = rand_indices[k + 1];
            xs[(k + 1) % 3][tid - 992] = data[(size_t)ni * DDIM + (tid - 992)];
        }

        // ---- dist^2 with XLA shfl.down(16,8,4,2,1) tree association ----
        // Packed reg j holds dims (2j, 2j+1); lane pairs (d, d+16) -> regs
        // (j, j+8). Fused form with 4 accumulators, association preserved:
        //   s4[j] = (m[j] + m[j+8]) + (m[j+4] + m[j+12])
        u64 s[4];
#pragma unroll
        for (int j = 0; j < 4; j++) {
            u64 t0, t1, t2, t3;
            ADD2(t0, x2[j],      nn[j]);      MUL2(t0, t0, t0);
            ADD2(t1, x2[j + 8],  nn[j + 8]);  MUL2(t1, t1, t1);
            ADD2(t2, x2[j + 4],  nn[j + 4]);  MUL2(t2, t2, t2);
            ADD2(t3, x2[j + 12], nn[j + 12]); MUL2(t3, t3, t3);
            ADD2(t0, t0, t1);   // m[j]   + m[j+8]   (offset-16 stage)
            ADD2(t2, t2, t3);   // m[j+4] + m[j+12]
            ADD2(s[j], t0, t2); // offset-8 stage
        }
        ADD2(s[0], s[0], s[2]); // offset-4 stage
        ADD2(s[1], s[1], s[3]);
        ADD2(s[0], s[0], s[1]); // offset-2 stage
        float lo, hi;
        unpack2(s[0], lo, hi);
        float ss   = __fadd_rn(lo, hi);  // offset-1 stage
        float dist = __fsqrt_rn(ss);

        // ---- block argmin on dist, ties -> lowest node index ----
        // dist >= 0, so float bits are order-isomorphic to u32.
        u32 bits = __float_as_uint(dist);
        u32 wmin = __reduce_min_sync(0xffffffffu, bits);
        u32 ball = __ballot_sync(0xffffffffu, bits == wmin);
        if (lane == 0) {
            wbits[wid] = wmin;
            widx[wid]  = (u32)((wid << 5) + (__ffs(ball) - 1));
        }
        __syncthreads();  // bar1
        if (wid == 0) {
            u32 b  = wbits[lane];
            u32 m2 = __reduce_min_sync(0xffffffffu, b);
            u32 bl = __ballot_sync(0xffffffffu, b == m2);
            if (lane == 0) winner = (int)widx[__ffs(bl) - 1];
            if (lane == 1) {
                // alpha schedule, exact rn chain, computed once per iter
                float kf = (float)k;
                float a  = __fsub_rn(0.05f,
                             __fmul_rn(0.04f, __fdiv_rn(kf, 2000.0f)));
                neg_alpha_sh = -a;
            }
        }
        __syncthreads();  // bar2
        const int   nearest = winner;
        const float nalpha  = neg_alpha_sh;

        // ---- deterministic threshold schedule ----
        th = fmaxf(th, 0.5f);

        // ---- masked neighborhood update: Chebyshev lattice distance ----
        int dr   = mr - (nearest >> 5); if (dr < 0) dr = -dr;
        int dc   = mc - (nearest & 31); if (dc < 0) dc = -dc;
        int cheb = dr > dc ? dr : dc;
        if ((float)cheb <= th) {
            // reference: n' = rn(n + rn(diff*alpha)); negated storage:
            // nn' = rn(nn + rn(diff*(-alpha))) — bit-identical under negation.
            // diff recomputed: nn unchanged since dist -> identical bits.
            u64 na = pack2(nalpha, nalpha);
#pragma unroll
            for (int j = 0; j < 16; j++) {
                u64 t;
                ADD2(t, x2[j], nn[j]);   // diff = x - node
                MUL2(t, t, na);          // rn(diff * -alpha)
                ADD2(nn[j], nn[j], t);   // rn(nn + t)
            }
        }
        th = __fadd_rn(th, -0.00975f);  // THRESH_STEP
    }

    // ---- write final nodes (un-negate, exact) ----
#pragma unroll
    for (int j = 0; j < 16; j++) {
        float a, b;
        unpack2(nn[j], a, b);
        out[tid * DDIM + 2 * j]     = -a;
        out[tid * DDIM + 2 * j + 1] = -b;
    }
}

extern "C" void kernel_launch(void* const* d_in, const int* in_sizes, int n_in,
                              void* d_out, int out_size) {
    // Robust input binding by element count:
    // data 500000*32, nodes 1024*32, nhbrdist 1024*1024 (unused), rand 2000.
    const float* data   = nullptr;
    const float* nodes  = nullptr;
    const int*   ridx   = nullptr;
    for (int i = 0; i < n_in; i++) {
        if      (in_sizes[i] == 500000 * 32) data  = (const float*)d_in[i];
        else if (in_sizes[i] == 1024 * 32)   nodes = (const float*)d_in[i];
        else if (in_sizes[i] == 2000)        ridx  = (const int*)d_in[i];
    }
    som_train_kernel<<<1, 1024>>>(data, nodes, ridx, (float*)d_out);
}

// round 15
// speedup vs baseline: 1.7987x; 1.0008x over previous
#include <cuda_runtime.h>
#include <cuda_bf16.h>

// torchSOM: sequential SOM training, 2000 iterations, single persistent CTA.
// nodes [1024,32] live NEGATED in registers (1 thread = 1 node row).
// Bit-exact XLA-GPU rounding: per-lane square (mul.rn) + shfl-down-tree
// association (16,8,4,2,1) + sqrt.rn; un-fused mul/add update; exact schedule.
// R13: restructured to fit 64 regs/thread (1024 thr) with NO spills:
//  - reduction tree fused into the diff loop (4 accumulators, same association)
//  - update recomputes diff (nn unchanged since dist -> bit-identical)
//  - alpha (fdiv) computed once in warp 0, broadcast via smem on bar2

#define DDIM 32
#define NITER_C 2000

typedef unsigned long long u64;
typedef unsigned int u32;

__device__ __forceinline__ u64 pack2(float lo, float hi) {
    u64 r;
    asm("mov.b64 %0, {%1, %2};" : "=l"(r) : "f"(lo), "f"(hi));
    return r;
}
__device__ __forceinline__ void unpack2(u64 v, float& lo, float& hi) {
    asm("mov.b64 {%0, %1}, %2;" : "=f"(lo), "=f"(hi) : "l"(v));
}
// Packed IEEE-rn f32x2 ops (per-lane semantics identical to scalar rn ops).
#define ADD2(out, a, b) \
    asm("add.rn.f32x2 %0, %1, %2;" : "=l"(out) : "l"(a), "l"(b))
#define MUL2(out, a, b) \
    asm("mul.rn.f32x2 %0, %1, %2;" : "=l"(out) : "l"(a), "l"(b))

__global__ __launch_bounds__(1024, 1)
void som_train_kernel(const float* __restrict__ data,
                      const float* __restrict__ nodes,
                      const int* __restrict__ rand_indices,
                      float* __restrict__ out)
{
    // x row triple buffer: the write at iter k+1 start is separated from the
    // last conflicting read (iter k-1's update loop) by iter k's barriers.
    __shared__ __align__(16) float xs[3][DDIM];
    __shared__ u32 wbits[32];
    __shared__ u32 widx[32];
    __shared__ int winner;
    __shared__ float neg_alpha_sh;

    const int tid  = threadIdx.x;
    const int lane = tid & 31;
    const int wid  = tid >> 5;
    const int mr   = tid >> 5;   // lattice row of this node
    const int mc   = tid & 31;   // lattice col of this node

    // Load this thread's node row, negated (negation is exact), packed.
    u64 nn[16];
#pragma unroll
    for (int j = 0; j < 16; j++) {
        float a = nodes[tid * DDIM + 2 * j];
        float b = nodes[tid * DDIM + 2 * j + 1];
        nn[j] = pack2(-a, -b);
    }

    // Preload x for iteration 0.
    if (tid < DDIM) {
        int i0 = rand_indices[0];
        xs[0][tid] = data[(size_t)i0 * DDIM + tid];
    }
    __syncthreads();

    float th = 20.0f;  // THRESH0

    for (int k = 0; k < NITER_C; k++) {
        const u64* __restrict__ x2 = (const u64*)xs[k % 3];

        // Prefetch next iteration's x row (warp 31, overlapped with compute).
        if (tid >= 992 && (k + 1) < NITER_C) {
            int ni = rand_indices[k + 1];
            xs[(k + 1) % 3][tid - 992] = data[(size_t)ni * DDIM + (tid - 992)];
        }

        // ---- dist^2 with XLA shfl.down(16,8,4,2,1) tree association ----
        // Packed reg j holds dims (2j, 2j+1); lane pairs (d, d+16) -> regs
        // (j, j+8). Fused form with 4 accumulators, association preserved:
        //   s4[j] = (m[j] + m[j+8]) + (m[j+4] + m[j+12])
        u64 s[4];
#pragma unroll
        for (int j = 0; j < 4; j++) {
            u64 t0, t1, t2, t3;
            ADD2(t0, x2[j],      nn[j]);      MUL2(t0, t0, t0);
            ADD2(t1, x2[j + 8],  nn[j + 8]);  MUL2(t1, t1, t1);
            ADD2(t2, x2[j + 4],  nn[j + 4]);  MUL2(t2, t2, t2);
            ADD2(t3, x2[j + 12], nn[j + 12]); MUL2(t3, t3, t3);
            ADD2(t0, t0, t1);   // m[j]   + m[j+8]   (offset-16 stage)
            ADD2(t2, t2, t3);   // m[j+4] + m[j+12]
            ADD2(s[j], t0, t2); // offset-8 stage
        }
        ADD2(s[0], s[0], s[2]); // offset-4 stage
        ADD2(s[1], s[1], s[3]);
        ADD2(s[0], s[0], s[1]); // offset-2 stage
        float lo, hi;
        unpack2(s[0], lo, hi);
        float ss   = __fadd_rn(lo, hi);  // offset-1 stage
        float dist = __fsqrt_rn(ss);

        // ---- block argmin on dist, ties -> lowest node index ----
        // dist >= 0, so float bits are order-isomorphic to u32.
        u32 bits = __float_as_uint(dist);
        u32 wmin = __reduce_min_sync(0xffffffffu, bits);
        u32 ball = __ballot_sync(0xffffffffu, bits == wmin);
        if (lane == 0) {
            wbits[wid] = wmin;
            widx[wid]  = (u32)((wid << 5) + (__ffs(ball) - 1));
        }
        __syncthreads();  // bar1
        if (wid == 0) {
            u32 b  = wbits[lane];
            u32 m2 = __reduce_min_sync(0xffffffffu, b);
            u32 bl = __ballot_sync(0xffffffffu, b == m2);
            if (lane == 0) winner = (int)widx[__ffs(bl) - 1];
            if (lane == 1) {
                // alpha schedule, exact rn chain, computed once per iter
                float kf = (float)k;
                float a  = __fsub_rn(0.05f,
                             __fmul_rn(0.04f, __fdiv_rn(kf, 2000.0f)));
                neg_alpha_sh = -a;
            }
        }
        __syncthreads();  // bar2
        const int   nearest = winner;
        const float nalpha  = neg_alpha_sh;

        // ---- deterministic threshold schedule ----
        th = fmaxf(th, 0.5f);

        // ---- masked neighborhood update: Chebyshev lattice distance ----
        int dr   = mr - (nearest >> 5); if (dr < 0) dr = -dr;
        int dc   = mc - (nearest & 31); if (dc < 0) dc = -dc;
        int cheb = dr > dc ? dr : dc;
        if ((float)cheb <= th) {
            // reference: n' = rn(n + rn(diff*alpha)); negated storage:
            // nn' = rn(nn + rn(diff*(-alpha))) — bit-identical under negation.
            // diff recomputed: nn unchanged since dist -> identical bits.
            u64 na = pack2(nalpha, nalpha);
#pragma unroll
            for (int j = 0; j < 16; j++) {
                u64 t;
                ADD2(t, x2[j], nn[j]);   // diff = x - node
                MUL2(t, t, na);          // rn(diff * -alpha)
                ADD2(nn[j], nn[j], t);   // rn(nn + t)
            }
        }
        th = __fadd_rn(th, -0.00975f);  // THRESH_STEP
    }

    // ---- write final nodes (un-negate, exact) ----
#pragma unroll
    for (int j = 0; j < 16; j++) {
        float a, b;
        unpack2(nn[j], a, b);
        out[tid * DDIM + 2 * j]     = -a;
        out[tid * DDIM + 2 * j + 1] = -b;
    }
}

extern "C" void kernel_launch(void* const* d_in, const int* in_sizes, int n_in,
                              void* d_out, int out_size) {
    // Robust input binding by element count:
    // data 500000*32, nodes 1024*32, nhbrdist 1024*1024 (unused), rand 2000.
    const float* data   = nullptr;
    const float* nodes  = nullptr;
    const int*   ridx   = nullptr;
    for (int i = 0; i < n_in; i++) {
        if      (in_sizes[i] == 500000 * 32) data  = (const float*)d_in[i];
        else if (in_sizes[i] == 1024 * 32)   nodes = (const float*)d_in[i];
        else if (in_sizes[i] == 2000)        ridx  = (const int*)d_in[i];
    }
    som_train_kernel<<<1, 1024>>>(data, nodes, ridx, (float*)d_out);
}